// round 14
// baseline (speedup 1.0000x reference)
#include <cuda_runtime.h>

// Pool_26517128085982: 2x2 mean pool, stride 2, x:(16,64,512,512) f32 -> (16,64,256,256) f32
// Converged at the DRAM roofline (~7.25 TB/s, 90.6% of spec; compulsory 1.342 GB).
// Band across 9 benches: 186.5-187.1us. Best: R6 config @ 186.50us.
// R14 — final mechanistic experiment: per-CTA WRITE BATCHING. Loads + compute as in the
// proven R6 kernel (flat grid, MLP=8, default caching), but outputs staged in 8KB smem
// and flushed after a barrier as two contiguous 4KB bursts per CTA. Goal: present writes
// to L2 in coarse address-dense batches to reduce DRAM R/W turnaround (the residual ~9%).
// If in-band/worse, the series is closed with R6 as the final kernel.

static constexpr int W_IN    = 512;
static constexpr int W_OUT   = 256;
static constexpr int H_OUT   = 256;
static constexpr int ROW4_IN  = W_IN / 4;          // 128 float4 per input row
static constexpr int ROW4_OUT = W_OUT / 4;         // 64  float4 per output row
static constexpr int IMG4_IN  = W_IN * W_IN / 4;   // 65536 float4 per input image
static constexpr int TPB      = 256;

__device__ __forceinline__ float4 pool4(const float4& a0, const float4& a1,
                                        const float4& b0, const float4& b1,
                                        const float4& k)
{
    float4 o;
    o.x = k.x * a0.x + k.y * a0.y + k.z * b0.x + k.w * b0.y;
    o.y = k.x * a0.z + k.y * a0.w + k.z * b0.z + k.w * b0.w;
    o.z = k.x * a1.x + k.y * a1.y + k.z * b1.x + k.w * b1.y;
    o.w = k.x * a1.z + k.y * a1.w + k.z * b1.z + k.w * b1.w;
    return o;
}

__global__ __launch_bounds__(TPB) void Pool_26517128085982_kernel(
    const float4* __restrict__ in,
    const float*  __restrict__ kern,   // 4 floats: k00 k01 k10 k11
    float4* __restrict__ out,
    int half_n4)                       // n_out4 / 2
{
    __shared__ float4 stage[2 * TPB];  // 8 KB: [0..255]=idx0 results, [256..511]=idx1

    int tid  = threadIdx.x;
    int idx0 = blockIdx.x * TPB + tid;
    if (idx0 >= half_n4) return;       // full blocks only in practice (half_n4 % TPB == 0)
    int idx1 = idx0 + half_n4;

    // idx -> (img, oh, oc4): 64 float4 per out row, 256 rows per image
    int oc4a = idx0 & (ROW4_OUT - 1);
    int oha  = (idx0 >> 6) & (H_OUT - 1);
    int imga = idx0 >> 14;
    int basea = imga * IMG4_IN + (oha << 1) * ROW4_IN + (oc4a << 1);

    int oc4b = idx1 & (ROW4_OUT - 1);
    int ohb  = (idx1 >> 6) & (H_OUT - 1);
    int imgb = idx1 >> 14;
    int baseb = imgb * IMG4_IN + (ohb << 1) * ROW4_IN + (oc4b << 1);

    // 8 independent LDG.128 (MLP=8), front-batched, default caching
    float4 a0 = in[basea];
    float4 a1 = in[basea + 1];
    float4 b0 = in[basea + ROW4_IN];
    float4 b1 = in[basea + ROW4_IN + 1];
    float4 c0 = in[baseb];
    float4 c1 = in[baseb + 1];
    float4 d0 = in[baseb + ROW4_IN];
    float4 d1 = in[baseb + ROW4_IN + 1];

    // kernel weights: broadcast load, L1-hit after first warp
    float4 k = *reinterpret_cast<const float4*>(kern);

    // Stage results in smem
    stage[tid]       = pool4(a0, a1, b0, b1, k);
    stage[tid + TPB] = pool4(c0, c1, d0, d1, k);

    __syncthreads();

    // Burst flush: two contiguous 4KB regions per CTA, all warps storing back-to-back.
    int blk0 = blockIdx.x * TPB;           // base of idx0 region
    out[blk0 + tid]            = stage[tid];
    out[blk0 + tid + half_n4]  = stage[tid + TPB];
}

extern "C" void kernel_launch(void* const* d_in, const int* in_sizes, int n_in,
                              void* d_out, int out_size)
{
    const float4* x    = (const float4*)d_in[0];
    const float*  kern = (const float*)d_in[1];
    float4*       out  = (float4*)d_out;

    int n_out4  = out_size / 4;          // 16,777,216 float4
    int half_n4 = n_out4 / 2;            // 8,388,608 threads
    int blocks  = (half_n4 + TPB - 1) / TPB;   // 32,768 blocks
    Pool_26517128085982_kernel<<<blocks, TPB>>>(x, kern, out, half_n4);
}